// round 2
// baseline (speedup 1.0000x reference)
#include <cuda_runtime.h>
#include <math.h>

#define Bb 8
#define Cc 512
#define Ll 2048
#define CQq 128

// Static device scratch (allocation-free rule: __device__ globals).
__device__ float g_q[Bb * CQq * Ll];        // 8 MiB
__device__ float g_k[Bb * CQq * Ll];        // 8 MiB
__device__ float g_v[(size_t)Bb * Cc * Ll]; // 32 MiB (gamma!=0 path only)
__device__ float g_att[(size_t)Bb * Ll * Ll];     // 128 MiB fallback
__device__ float g_outbuf[(size_t)Bb * Cc * Ll];  // 32 MiB fallback

// ---------------------------------------------------------------------------
// Generic 1x1 conv (channel GEMM): out[b,m,n] = sum_k W[m,k]*x[b,k,n] + bias[m]
// Tile 128x128xBK8, 256 threads, 8x8 per thread.
// GATE=1: run only when gamma[0] != 0 (v projection on the dead path).
// ---------------------------------------------------------------------------
template <int GATE>
__global__ __launch_bounds__(256)
void conv1x1_kernel(const float* __restrict__ W, const float* __restrict__ bias,
                    const float* __restrict__ x, float* __restrict__ out,
                    int M, const float* __restrict__ gamma)
{
    if (GATE) { if (gamma[0] == 0.0f) return; }
    const int b  = blockIdx.z;
    const int m0 = blockIdx.y * 128;
    const int n0 = blockIdx.x * 128;

    __shared__ float As[8][128];   // As[k][m]
    __shared__ float Bs[8][128];   // Bs[k][n]

    const int tid = threadIdx.x;
    const int tx = tid % 16, ty = tid / 16;

    const float* xb = x + (size_t)b * Cc * Ll;

    const int aRow = tid >> 1;          // 0..127 (m)
    const int aCol = (tid & 1) * 4;     // 0 / 4  (k)
    const int bRow = tid >> 5;          // 0..7   (k)
    const int bCol = (tid & 31) * 4;    // 0..124 (n)

    float acc[8][8];
    #pragma unroll
    for (int i = 0; i < 8; i++)
        #pragma unroll
        for (int j = 0; j < 8; j++) acc[i][j] = 0.0f;

    for (int k0 = 0; k0 < Cc; k0 += 8) {
        float4 a = *(const float4*)&W[(size_t)(m0 + aRow) * Cc + k0 + aCol];
        As[aCol + 0][aRow] = a.x;
        As[aCol + 1][aRow] = a.y;
        As[aCol + 2][aRow] = a.z;
        As[aCol + 3][aRow] = a.w;
        *(float4*)&Bs[bRow][bCol] =
            *(const float4*)&xb[(size_t)(k0 + bRow) * Ll + n0 + bCol];
        __syncthreads();

        #pragma unroll
        for (int k = 0; k < 8; k++) {
            float rm[8], rn[8];
            #pragma unroll
            for (int i = 0; i < 8; i++) rm[i] = As[k][ty * 8 + i];
            #pragma unroll
            for (int j = 0; j < 8; j++) rn[j] = Bs[k][tx * 8 + j];
            #pragma unroll
            for (int i = 0; i < 8; i++)
                #pragma unroll
                for (int j = 0; j < 8; j++)
                    acc[i][j] = fmaf(rm[i], rn[j], acc[i][j]);
        }
        __syncthreads();
    }

    float* ob = out + (size_t)b * M * Ll;
    #pragma unroll
    for (int i = 0; i < 8; i++) {
        const int m = m0 + ty * 8 + i;
        const float bb = bias[m];
        float* po = ob + (size_t)m * Ll + n0 + tx * 8;
        float4 v0 = make_float4(acc[i][0] + bb, acc[i][1] + bb,
                                acc[i][2] + bb, acc[i][3] + bb);
        float4 v1 = make_float4(acc[i][4] + bb, acc[i][5] + bb,
                                acc[i][6] + bb, acc[i][7] + bb);
        *(float4*)po       = v0;
        *(float4*)(po + 4) = v1;
    }
}

// ---------------------------------------------------------------------------
// energy[b,i,j] = sum_d q[b,d,i] * k[b,d,j]   (TN GEMM, K = CQ = 128)
// ---------------------------------------------------------------------------
__global__ __launch_bounds__(256)
void energy_kernel(float* __restrict__ E)
{
    const int b  = blockIdx.z;
    const int i0 = blockIdx.y * 128;
    const int j0 = blockIdx.x * 128;

    __shared__ float Qs[8][128];   // Qs[d][i]
    __shared__ float Ks[8][128];   // Ks[d][j]

    const int tid = threadIdx.x;
    const int tx = tid % 16, ty = tid / 16;
    const int lRow = tid >> 5;          // 0..7  (d)
    const int lCol = (tid & 31) * 4;    // 0..124

    const float* qb = g_q + (size_t)b * CQq * Ll;
    const float* kb = g_k + (size_t)b * CQq * Ll;

    float acc[8][8];
    #pragma unroll
    for (int i = 0; i < 8; i++)
        #pragma unroll
        for (int j = 0; j < 8; j++) acc[i][j] = 0.0f;

    for (int d0 = 0; d0 < CQq; d0 += 8) {
        *(float4*)&Qs[lRow][lCol] =
            *(const float4*)&qb[(size_t)(d0 + lRow) * Ll + i0 + lCol];
        *(float4*)&Ks[lRow][lCol] =
            *(const float4*)&kb[(size_t)(d0 + lRow) * Ll + j0 + lCol];
        __syncthreads();

        #pragma unroll
        for (int k = 0; k < 8; k++) {
            float rm[8], rn[8];
            #pragma unroll
            for (int i = 0; i < 8; i++) rm[i] = Qs[k][ty * 8 + i];
            #pragma unroll
            for (int j = 0; j < 8; j++) rn[j] = Ks[k][tx * 8 + j];
            #pragma unroll
            for (int i = 0; i < 8; i++)
                #pragma unroll
                for (int j = 0; j < 8; j++)
                    acc[i][j] = fmaf(rm[i], rn[j], acc[i][j]);
        }
        __syncthreads();
    }

    float* eb = E + (size_t)b * Ll * Ll;
    #pragma unroll
    for (int i = 0; i < 8; i++) {
        float* po = eb + (size_t)(i0 + ty * 8 + i) * Ll + j0 + tx * 8;
        *(float4*)po       = make_float4(acc[i][0], acc[i][1], acc[i][2], acc[i][3]);
        *(float4*)(po + 4) = make_float4(acc[i][4], acc[i][5], acc[i][6], acc[i][7]);
    }
}

// ---------------------------------------------------------------------------
// In-place row softmax over last axis. One block (256 thr) per row of 2048.
// ---------------------------------------------------------------------------
__global__ __launch_bounds__(256)
void softmax_kernel(float* __restrict__ att)
{
    const size_t row = blockIdx.x;          // b*L + i
    float* p = att + row * (size_t)Ll;
    const int tid = threadIdx.x;

    float vals[8];
    float m = -INFINITY;
    #pragma unroll
    for (int j = 0; j < 8; j++) {
        vals[j] = p[tid + j * 256];
        m = fmaxf(m, vals[j]);
    }
    __shared__ float red[256];
    red[tid] = m;
    __syncthreads();
    #pragma unroll
    for (int s = 128; s > 0; s >>= 1) {
        if (tid < s) red[tid] = fmaxf(red[tid], red[tid + s]);
        __syncthreads();
    }
    m = red[0];
    __syncthreads();

    float sum = 0.0f;
    #pragma unroll
    for (int j = 0; j < 8; j++) {
        vals[j] = expf(vals[j] - m);
        sum += vals[j];
    }
    red[tid] = sum;
    __syncthreads();
    #pragma unroll
    for (int s = 128; s > 0; s >>= 1) {
        if (tid < s) red[tid] += red[tid + s];
        __syncthreads();
    }
    const float inv = 1.0f / red[0];
    #pragma unroll
    for (int j = 0; j < 8; j++) p[tid + j * 256] = vals[j] * inv;
}

// ---------------------------------------------------------------------------
// gamma == 0 fast path: out = x  (vectorized copy). Gated on gamma[0]==0.
// ---------------------------------------------------------------------------
__global__ __launch_bounds__(256)
void copy_x_kernel(const float* __restrict__ x, float* __restrict__ out,
                   const float* __restrict__ gamma)
{
    if (gamma[0] != 0.0f) return;
    const size_t idx = ((size_t)blockIdx.x * 256 + threadIdx.x) * 4;
    *(float4*)&out[idx] = *(const float4*)&x[idx];
}

// ---------------------------------------------------------------------------
// gamma != 0 path: out[b,c,i] = gamma * sum_j v[b,c,j]*att[b,i,j] + x[b,c,i]
// (A * B^T tiled GEMM, K = L = 2048). Gated on gamma[0]!=0.
// ---------------------------------------------------------------------------
__global__ __launch_bounds__(256)
void outgemm_kernel(const float* __restrict__ att, const float* __restrict__ x,
                    float* __restrict__ out, const float* __restrict__ gamma)
{
    const float g = gamma[0];
    if (g == 0.0f) return;
    const int b  = blockIdx.z;
    const int c0 = blockIdx.y * 128;
    const int i0 = blockIdx.x * 128;

    __shared__ float Vs[8][128];   // Vs[j][c]
    __shared__ float Ts[8][128];   // Ts[j][i]

    const int tid = threadIdx.x;
    const int tx = tid % 16, ty = tid / 16;
    const int aRow = tid >> 1;        // 0..127
    const int aCol = (tid & 1) * 4;   // 0 / 4 (j)

    const float* vb = g_v + (size_t)b * Cc * Ll;
    const float* ab = att + (size_t)b * Ll * Ll;

    float acc[8][8];
    #pragma unroll
    for (int i = 0; i < 8; i++)
        #pragma unroll
        for (int j = 0; j < 8; j++) acc[i][j] = 0.0f;

    for (int j0 = 0; j0 < Ll; j0 += 8) {
        float4 a = *(const float4*)&vb[(size_t)(c0 + aRow) * Ll + j0 + aCol];
        Vs[aCol + 0][aRow] = a.x;
        Vs[aCol + 1][aRow] = a.y;
        Vs[aCol + 2][aRow] = a.z;
        Vs[aCol + 3][aRow] = a.w;
        float4 t = *(const float4*)&ab[(size_t)(i0 + aRow) * Ll + j0 + aCol];
        Ts[aCol + 0][aRow] = t.x;
        Ts[aCol + 1][aRow] = t.y;
        Ts[aCol + 2][aRow] = t.z;
        Ts[aCol + 3][aRow] = t.w;
        __syncthreads();

        #pragma unroll
        for (int k = 0; k < 8; k++) {
            float rm[8], rn[8];
            #pragma unroll
            for (int i = 0; i < 8; i++) rm[i] = Vs[k][ty * 8 + i];
            #pragma unroll
            for (int j = 0; j < 8; j++) rn[j] = Ts[k][tx * 8 + j];
            #pragma unroll
            for (int i = 0; i < 8; i++)
                #pragma unroll
                for (int j = 0; j < 8; j++)
                    acc[i][j] = fmaf(rm[i], rn[j], acc[i][j]);
        }
        __syncthreads();
    }

    #pragma unroll
    for (int i = 0; i < 8; i++) {
        const size_t off = (size_t)b * Cc * Ll + (size_t)(c0 + ty * 8 + i) * Ll
                         + i0 + tx * 8;
        #pragma unroll
        for (int j = 0; j < 8; j++)
            out[off + j] = g * acc[i][j] + x[off + j];
    }
}

// ---------------------------------------------------------------------------
extern "C" void kernel_launch(void* const* d_in, const int* in_sizes, int n_in,
                              void* d_out, int out_size)
{
    (void)in_sizes; (void)n_in;
    const float* x     = (const float*)d_in[0];
    const float* q_w   = (const float*)d_in[1];
    const float* q_b   = (const float*)d_in[2];
    const float* k_w   = (const float*)d_in[3];
    const float* k_b   = (const float*)d_in[4];
    const float* v_w   = (const float*)d_in[5];
    const float* v_b   = (const float*)d_in[6];
    const float* gamma = (const float*)d_in[7];

    const size_t BCL = (size_t)Bb * Cc * Ll;        // 8388608
    const size_t BLL = (size_t)Bb * Ll * Ll;        // 33554432

    float* out_ptr;
    float* att_ptr;
    if ((size_t)out_size >= BCL + BLL) {
        out_ptr = (float*)d_out;
        att_ptr = (float*)d_out + BCL;
    } else if ((size_t)out_size == BLL) {
        cudaGetSymbolAddress((void**)&out_ptr, g_outbuf);
        att_ptr = (float*)d_out;
    } else {
        out_ptr = (float*)d_out;
        cudaGetSymbolAddress((void**)&att_ptr, g_att);
    }
    float* qbuf; cudaGetSymbolAddress((void**)&qbuf, g_q);
    float* kbuf; cudaGetSymbolAddress((void**)&kbuf, g_k);
    float* vbuf; cudaGetSymbolAddress((void**)&vbuf, g_v);

    dim3 blk(256);

    // q and k projections (ungated)
    conv1x1_kernel<0><<<dim3(Ll / 128, CQq / 128, Bb), blk>>>(q_w, q_b, x, qbuf, CQq, gamma);
    conv1x1_kernel<0><<<dim3(Ll / 128, CQq / 128, Bb), blk>>>(k_w, k_b, x, kbuf, CQq, gamma);

    // energy -> attention region, softmax in place
    energy_kernel<<<dim3(Ll / 128, Ll / 128, Bb), blk>>>(att_ptr);
    softmax_kernel<<<dim3(Bb * Ll), blk>>>(att_ptr);

    // out path: gamma==0 -> copy; gamma!=0 -> v conv + out GEMM
    copy_x_kernel<<<dim3((unsigned)(BCL / (256 * 4))), blk>>>(x, out_ptr, gamma);
    conv1x1_kernel<1><<<dim3(Ll / 128, Cc / 128, Bb), blk>>>(v_w, v_b, x, vbuf, Cc, gamma);
    outgemm_kernel<<<dim3(Ll / 128, Cc / 128, Bb), blk>>>(att_ptr, x, out_ptr, gamma);
}